// round 7
// baseline (speedup 1.0000x reference)
#include <cuda_runtime.h>

// ---------------------------------------------------------------------------
// MSDeformAttn fusion: value conv -> off/attn conv -> flow-guided deformable
// sampling -> output conv.  B=2, T=3, C=256, H=W=64, M=8, P=4, DH=32.
// R5: conv FMA-pipe-bound: 4px x 8cout register tile (geometry fixed vs R4),
// input patch cached in registers across taps, f32x2 packed math.
// ---------------------------------------------------------------------------

#define NB   2
#define NT   3
#define NC   256
#define NH   64
#define NW   64
#define NHW  4096
#define NM   8
#define NP   4
#define NDH  32

typedef unsigned long long ull;

// Scratch (zero-init .bss, not allocations)
__device__ __align__(16) float g_value[NB*NT*NHW*NC];     // NHWC per (b,t)
__device__ __align__(16) float g_offattn[NB*NHW*288];     // 192 off + 96 attn
__device__ __align__(16) float g_attnout[NB*NC*NHW];      // NCHW attention output

// ---- packed f32x2 helpers (sm_103a dual-rate fp32 path; PTX-only) ----------
__device__ __forceinline__ ull pack2(float a, float b) {
    union { float2 f; ull u; } t; t.f = make_float2(a, b); return t.u;
}
__device__ __forceinline__ float2 unpack2(ull v) {
    union { float2 f; ull u; } t; t.u = v; return t.f;
}
__device__ __forceinline__ void ffma2(ull& d, ull a, ull b) {
#if defined(__CUDA_ARCH__) && (__CUDA_ARCH__ >= 1000)
    asm("fma.rn.f32x2 %0, %1, %2, %0;" : "+l"(d) : "l"(a), "l"(b));
#else
    float2 df = unpack2(d), af = unpack2(a), bf = unpack2(b);
    df.x = fmaf(af.x, bf.x, df.x); df.y = fmaf(af.y, bf.y, df.y);
    d = pack2(df.x, df.y);
#endif
}

// ---------------------------------------------------------------------------
// Direct 3x3 SAME conv, NCHW input, fp32.
// Block: 256 threads, pixel tile 32(x) x 16(y), 16 couts.
//   cog = tid&1 -> couts cog*8..+7
//   q = tid>>1 (0..127): px0=(q&7)*4 (covers 32), py=q>>3 (covers 16)
//   thread computes 4x1 pixels x 8 couts (4 px x 4 f32x2 pairs = 32 floats).
// Inner: per 8-cin slice, per ci: 3x6 patch -> registers, then 9 taps of
//   16 independent FFMA2 each.  144 FFMA2 vs ~45 cheap LDS per ci.
// MODE 0: value conv -> g_value NHWC + mask
// MODE 1: off(192)+attn(96) conv, 18 cout groups -> g_offattn
// MODE 2: out conv (in=g_attnout) -> gout NCHW (final d_out)
// ---------------------------------------------------------------------------
template<int CIN, int MODE>
__global__ __launch_bounds__(256, 2)
void conv3x3(const float* __restrict__ gin,
             const float* __restrict__ w0, const float* __restrict__ b0,
             const float* __restrict__ w1, const float* __restrict__ b1,
             float* __restrict__ gout,
             const unsigned char* __restrict__ mask)
{
    constexpr int NCG = (MODE == 1) ? 18 : 16;
    const int img = blockIdx.z / NCG;
    const int zg  = blockIdx.z % NCG;
    const int tx0 = blockIdx.x * 32;
    const int ty0 = blockIdx.y * 16;
    const int tid = threadIdx.x;
    const int cog = tid & 1;
    const int q   = tid >> 1;
    const int px0 = (q & 7) * 4;
    const int py  = q >> 3;          // 0..15

    const float* wsrc; const float* bsrc; int corow0;
    if (MODE == 1 && zg >= 12) { wsrc = w1; bsrc = b1; corow0 = zg*16 - 192; }
    else                       { wsrc = w0; bsrc = b0; corow0 = zg*16;       }

    const float* src    = (MODE == 2) ? (const float*)g_attnout : gin;
    const float* inbase = src + (size_t)img * CIN * NHW;

    __shared__ float s_in[8][18][36];   // rows: gy ty0-1..ty0+16; cols 34 (+2 pad)
    __shared__ float s_w[8*9*16];       // [(ci*9+tap)*16 + co]

    ull acc[4][4];                      // [pixel ix][cout pair]
    {
        const float* bp = bsrc + corow0 + cog*8;
        ull b01 = pack2(bp[0], bp[1]);
        ull b23 = pack2(bp[2], bp[3]);
        ull b45 = pack2(bp[4], bp[5]);
        ull b67 = pack2(bp[6], bp[7]);
        #pragma unroll
        for (int p = 0; p < 4; p++) {
            acc[p][0] = b01; acc[p][1] = b23; acc[p][2] = b45; acc[p][3] = b67;
        }
    }

    for (int cin0 = 0; cin0 < CIN; cin0 += 8) {
        // stage input halo patch 34x18 x 8 cin
        for (int i = tid; i < 8*612; i += 256) {       // 612 = 18*34
            int ci = i / 612; int r = i - ci*612;
            int yy = r / 34;  int xx = r - yy*34;
            int gy = ty0 + yy - 1, gx = tx0 + xx - 1;
            float v = 0.f;
            if ((unsigned)gy < 64u && (unsigned)gx < 64u)
                v = inbase[(size_t)(cin0 + ci) * NHW + gy*64 + gx];
            s_in[ci][yy][xx] = v;
        }
        // stage weights: 16 couts x 8 cin x 9 taps, co-contiguous
        for (int i = tid; i < 16*72; i += 256) {
            int co = i / 72; int r = i - co*72;        // r = ci*9 + tap
            s_w[r*16 + co] = wsrc[(size_t)(corow0 + co) * CIN * 9 + cin0*9 + r];
        }
        __syncthreads();

        #pragma unroll 1
        for (int ci = 0; ci < 8; ci++) {
            // cache 3x6 input patch in registers (s_in rows py..py+2,
            // cols px0..px0+5) -- output row py needs input rows py-1..py+1,
            // which are s_in rows py..py+2 (row 0 = gy ty0-1).
            float pt[3][6];
            #pragma unroll
            for (int ry = 0; ry < 3; ry++) {
                const float2* rp = reinterpret_cast<const float2*>(&s_in[ci][py + ry][px0]);
                float2 v0 = rp[0], v1 = rp[1], v2 = rp[2];
                pt[ry][0] = v0.x; pt[ry][1] = v0.y;
                pt[ry][2] = v1.x; pt[ry][3] = v1.y;
                pt[ry][4] = v2.x; pt[ry][5] = v2.y;
            }
            #pragma unroll
            for (int tap = 0; tap < 9; tap++) {
                const int dy = tap / 3, dx = tap % 3;
                const ull* wp = reinterpret_cast<const ull*>(&s_w[(ci*9 + tap)*16 + cog*8]);
                ull w0 = wp[0], w1 = wp[1], w2 = wp[2], w3 = wp[3];
                #pragma unroll
                for (int ix = 0; ix < 4; ix++) {
                    float v = pt[dy][ix + dx];
                    ull vv = pack2(v, v);
                    ull* a = acc[ix];
                    ffma2(a[0], vv, w0);
                    ffma2(a[1], vv, w1);
                    ffma2(a[2], vv, w2);
                    ffma2(a[3], vv, w3);
                }
            }
        }
        __syncthreads();
    }

    const int gy = ty0 + py;
    #pragma unroll
    for (int ix = 0; ix < 4; ix++) {
        const int gx = tx0 + px0 + ix;
        float2 a0 = unpack2(acc[ix][0]);
        float2 a1 = unpack2(acc[ix][1]);
        float2 a2 = unpack2(acc[ix][2]);
        float2 a3 = unpack2(acc[ix][3]);
        float4 lo = make_float4(a0.x, a0.y, a1.x, a1.y);
        float4 hi = make_float4(a2.x, a2.y, a3.x, a3.y);
        if (MODE == 0) {
            size_t pidx = (size_t)img * NHW + gy*64 + gx;  // img = b*T + t
            if (mask[pidx]) {
                lo = make_float4(0.f, 0.f, 0.f, 0.f);
                hi = make_float4(0.f, 0.f, 0.f, 0.f);
            }
            float* dst = &g_value[pidx*NC + zg*16 + cog*8];
            *reinterpret_cast<float4*>(dst)     = lo;
            *reinterpret_cast<float4*>(dst + 4) = hi;
        } else if (MODE == 1) {
            size_t base = ((size_t)img * NHW + gy*64 + gx) * 288 + zg*16 + cog*8;
            *reinterpret_cast<float4*>(&g_offattn[base])     = lo;
            *reinterpret_cast<float4*>(&g_offattn[base + 4]) = hi;
        } else {
            const int co = zg*16 + cog*8;
            size_t base = ((size_t)img * NC + co) * NHW + gy*64 + gx;
            gout[base]           = lo.x;
            gout[base +   NHW]   = lo.y;
            gout[base + 2*NHW]   = lo.z;
            gout[base + 3*NHW]   = lo.w;
            gout[base + 4*NHW]   = hi.x;
            gout[base + 5*NHW]   = hi.y;
            gout[base + 6*NHW]   = hi.z;
            gout[base + 7*NHW]   = hi.w;
        }
    }
}

// ---------------------------------------------------------------------------
// Deformable sampling.  One warp per (b, pixel, head); lane = head channel.
// softmax over T*P=12, flow-guided locations, bilinear zero-pad gather from
// g_value (NHWC -> 128B coalesced per corner), write NCHW g_attnout.
// ---------------------------------------------------------------------------
__global__ __launch_bounds__(256)
void deform_sample(const float* __restrict__ ref,
                   const float* __restrict__ flow_f,
                   const float* __restrict__ flow_b)
{
    const int wg   = blockIdx.x * 8 + (threadIdx.x >> 5);
    const int lane = threadIdx.x & 31;
    const int m   = wg & 7;
    const int pix = (wg >> 3) & 4095;
    const int b   = wg >> 15;

    const float* oa = g_offattn + (size_t)(b * NHW + pix) * 288;

    // softmax over the 12 (t,p) attention logits of this head
    float att[12];
    float mx = -1e30f;
    #pragma unroll
    for (int i = 0; i < 12; i++) { att[i] = oa[192 + m*12 + i]; mx = fmaxf(mx, att[i]); }
    float s = 0.f;
    #pragma unroll
    for (int i = 0; i < 12; i++) { att[i] = __expf(att[i] - mx); s += att[i]; }
    const float inv = 1.0f / s;
    #pragma unroll
    for (int i = 0; i < 12; i++) att[i] *= inv;

    float acc = 0.f;
    const float* vb = g_value + (size_t)(b * NT) * NHW * NC + m*NDH + lane;
    const float* rp = ref + (size_t)(b * NHW + pix) * (NT*2);

    #pragma unroll
    for (int t = 0; t < NT; t++) {
        // flow: t=0 <- flow_backward[b,0,:], t=1 <- 0, t=2 <- flow_forward[b,1,:]
        float fx = 0.f, fy = 0.f;
        if (t == 0) { fx = flow_b[b*16384 + pix];        fy = flow_b[b*16384 + 4096 + pix]; }
        if (t == 2) { fx = flow_f[b*16384 + 8192 + pix]; fy = flow_f[b*16384 + 8192 + 4096 + pix]; }
        // sample coord = ref*W + off + flow - 0.5  (normalizer W=H=64 cancels)
        const float rx = rp[t*2 + 0] * 64.f - 0.5f + fx;
        const float ry = rp[t*2 + 1] * 64.f - 0.5f + fy;
        const float* vt = vb + (size_t)t * NHW * NC;
        #pragma unroll
        for (int p = 0; p < NP; p++) {
            const float sx = rx + oa[(m*NT + t)*8 + p*2 + 0];
            const float sy = ry + oa[(m*NT + t)*8 + p*2 + 1];
            const float x0f = floorf(sx), y0f = floorf(sy);
            const float wx = sx - x0f, wy = sy - y0f;
            const int x0 = (int)x0f, y0 = (int)y0f;
            const float a = att[t*4 + p];
            const float w00 = (1.f - wx) * (1.f - wy) * a;
            const float w10 = wx * (1.f - wy) * a;
            const float w01 = (1.f - wx) * wy * a;
            const float w11 = wx * wy * a;
            const bool xv0 = (unsigned)x0       < 64u;
            const bool xv1 = (unsigned)(x0 + 1) < 64u;
            if ((unsigned)y0 < 64u) {
                const float* r0 = vt + (size_t)(y0*64) * NC;
                if (xv0) acc += w00 * r0[(size_t)x0 * NC];
                if (xv1) acc += w10 * r0[(size_t)(x0 + 1) * NC];
            }
            if ((unsigned)(y0 + 1) < 64u) {
                const float* r1 = vt + (size_t)((y0 + 1)*64) * NC;
                if (xv0) acc += w01 * r1[(size_t)x0 * NC];
                if (xv1) acc += w11 * r1[(size_t)(x0 + 1) * NC];
            }
        }
    }
    g_attnout[(size_t)(b*NC + m*NDH + lane) * NHW + pix] = acc;
}

// ---------------------------------------------------------------------------
// metadata order:
// 0 query 1 reference_points 2 input_flatten 3 spatial_shapes 4 level_start
// 5 padding_mask(bool) 6 flow_forward 7 flow_backward 8 w_value 9 b_value
// 10 w_off 11 b_off 12 w_attn 13 b_attn 14 w_out 15 b_out ; out (B,C,H,W) f32
// ---------------------------------------------------------------------------
extern "C" void kernel_launch(void* const* d_in, const int* in_sizes, int n_in,
                              void* d_out, int out_size)
{
    const float* query         = (const float*)d_in[0];
    const float* refp          = (const float*)d_in[1];
    const float* input_flatten = (const float*)d_in[2];
    const unsigned char* mask  = (const unsigned char*)d_in[5];
    const float* flow_f        = (const float*)d_in[6];
    const float* flow_b        = (const float*)d_in[7];
    const float* w_value       = (const float*)d_in[8];
    const float* b_value       = (const float*)d_in[9];
    const float* w_off         = (const float*)d_in[10];
    const float* b_off         = (const float*)d_in[11];
    const float* w_attn        = (const float*)d_in[12];
    const float* b_attn        = (const float*)d_in[13];
    const float* w_out         = (const float*)d_in[14];
    const float* b_out         = (const float*)d_in[15];
    float* out = (float*)d_out;

    // 1) value conv: 6 images of 256ch -> g_value NHWC (+mask)
    conv3x3<256, 0><<<dim3(2, 4, 6*16), 256>>>(input_flatten, w_value, b_value,
                                               nullptr, nullptr, nullptr, mask);
    // 2) fused offset(192)+attn(96) conv: 2 images of 768ch -> g_offattn
    conv3x3<768, 1><<<dim3(2, 4, 2*18), 256>>>(query, w_off, b_off,
                                               w_attn, b_attn, nullptr, nullptr);
    // 3) deformable sampling: 65536 warps -> g_attnout NCHW
    deform_sample<<<8192, 256>>>(refp, flow_f, flow_b);
    // 4) output conv: 2 images of 256ch -> final d_out NCHW
    conv3x3<256, 2><<<dim3(2, 4, 2*16), 256>>>(nullptr, w_out, b_out,
                                               nullptr, nullptr, out, nullptr);
}

// round 8
// speedup vs baseline: 1.5267x; 1.5267x over previous
#include <cuda_runtime.h>

// ---------------------------------------------------------------------------
// MSDeformAttn fusion: value conv -> off/attn conv -> flow-guided deformable
// sampling -> output conv.  B=2, T=3, C=256, H=W=64, M=8, P=4, DH=32.
// R8: R3 geometry (proven) + pre-duplicated (v,v) input staging so the inner
// loop is pure LDS.128/LDS.64 + FFMA2 (no pack MOVs), patch cached in regs.
// ---------------------------------------------------------------------------

#define NB   2
#define NT   3
#define NC   256
#define NH   64
#define NW   64
#define NHW  4096
#define NM   8
#define NP   4
#define NDH  32

typedef unsigned long long ull;

// Scratch (zero-init .bss, not allocations)
__device__ __align__(16) float g_value[NB*NT*NHW*NC];     // NHWC per (b,t)
__device__ __align__(16) float g_offattn[NB*NHW*288];     // 192 off + 96 attn
__device__ __align__(16) float g_attnout[NB*NC*NHW];      // NCHW attention output

// ---- packed f32x2 helpers (sm_103a dual-rate fp32 path; PTX-only) ----------
__device__ __forceinline__ ull pack2(float a, float b) {
    union { float2 f; ull u; } t; t.f = make_float2(a, b); return t.u;
}
__device__ __forceinline__ float2 unpack2(ull v) {
    union { float2 f; ull u; } t; t.u = v; return t.f;
}
__device__ __forceinline__ void ffma2(ull& d, ull a, ull b) {
#if defined(__CUDA_ARCH__) && (__CUDA_ARCH__ >= 1000)
    asm("fma.rn.f32x2 %0, %1, %2, %0;" : "+l"(d) : "l"(a), "l"(b));
#else
    float2 df = unpack2(d), af = unpack2(a), bf = unpack2(b);
    df.x = fmaf(af.x, bf.x, df.x); df.y = fmaf(af.y, bf.y, df.y);
    d = pack2(df.x, df.y);
#endif
}

// ---------------------------------------------------------------------------
// Direct 3x3 SAME conv, NCHW input, fp32.
// Block: 256 threads = 16x16 pixel tile x 16 couts.
//   cog = tid&3 -> couts cog*4..+3 ; quad = tid>>2 -> 2x2 pixel quad
//   px0=(quad&7)*2, py0=(quad>>3)*2.
// s_in holds each input value DUPLICATED as (v,v) pairs so the inner loop is
// LDS.128 (patch, cached in regs across taps) + LDS.64 (weights) + FFMA2.
// MODE 0: value conv -> g_value NHWC + mask
// MODE 1: off(192)+attn(96) conv, 18 cout groups -> g_offattn
// MODE 2: out conv (in=g_attnout) -> gout NCHW (final d_out)
// ---------------------------------------------------------------------------
template<int CIN, int MODE>
__global__ __launch_bounds__(256, 3)
void conv3x3(const float* __restrict__ gin,
             const float* __restrict__ w0, const float* __restrict__ b0,
             const float* __restrict__ w1, const float* __restrict__ b1,
             float* __restrict__ gout,
             const unsigned char* __restrict__ mask)
{
    constexpr int NCG = (MODE == 1) ? 18 : 16;
    const int img = blockIdx.z / NCG;
    const int zg  = blockIdx.z % NCG;
    const int tx0 = blockIdx.x * 16;
    const int ty0 = blockIdx.y * 16;
    const int tid = threadIdx.x;
    const int cog  = tid & 3;
    const int quad = tid >> 2;
    const int px0 = (quad & 7) * 2;
    const int py0 = (quad >> 3) * 2;

    const float* wsrc; const float* bsrc; int corow0;
    if (MODE == 1 && zg >= 12) { wsrc = w1; bsrc = b1; corow0 = zg*16 - 192; }
    else                       { wsrc = w0; bsrc = b0; corow0 = zg*16;       }

    const float* src    = (MODE == 2) ? (const float*)g_attnout : gin;
    const float* inbase = src + (size_t)img * CIN * NHW;

    __shared__ float s_in[8][18][40];   // duplicated pairs: col x -> [2x],[2x+1]
    __shared__ float s_w[8*9*16];       // [(ci*9+tap)*16 + co]

    ull acc[4][2];
    {
        const float* bp = bsrc + corow0 + cog*4;
        ull p01 = pack2(bp[0], bp[1]);
        ull p23 = pack2(bp[2], bp[3]);
        #pragma unroll
        for (int p = 0; p < 4; p++) { acc[p][0] = p01; acc[p][1] = p23; }
    }

    for (int cin0 = 0; cin0 < CIN; cin0 += 8) {
        // stage input halo 18x18 x 8 cin, duplicated (v,v)
        for (int i = tid; i < 8*324; i += 256) {
            int ci = i / 324; int r = i - ci*324;
            int yy = r / 18;  int xx = r - yy*18;
            int gy = ty0 + yy - 1, gx = tx0 + xx - 1;
            float v = 0.f;
            if ((unsigned)gy < 64u && (unsigned)gx < 64u)
                v = inbase[(size_t)(cin0 + ci) * NHW + gy*64 + gx];
            *reinterpret_cast<float2*>(&s_in[ci][yy][xx*2]) = make_float2(v, v);
        }
        // stage weights: 16 couts x 8 cin x 9 taps, co-contiguous
        for (int i = tid; i < 16*72; i += 256) {
            int co = i / 72; int r = i - co*72;            // r = ci*9 + tap
            s_w[r*16 + co] = wsrc[(size_t)(corow0 + co) * CIN * 9 + cin0*9 + r];
        }
        __syncthreads();

        #pragma unroll 1
        for (int ci = 0; ci < 8; ci++) {
            // cache 4x4 duplicated patch in regs: rows py0..py0+3, cols px0..px0+3
            ull pt[4][4];
            #pragma unroll
            for (int ry = 0; ry < 4; ry++) {
                float4 t0 = *reinterpret_cast<const float4*>(&s_in[ci][py0 + ry][px0*2]);
                float4 t1 = *reinterpret_cast<const float4*>(&s_in[ci][py0 + ry][px0*2 + 4]);
                pt[ry][0] = pack2(t0.x, t0.y);
                pt[ry][1] = pack2(t0.z, t0.w);
                pt[ry][2] = pack2(t1.x, t1.y);
                pt[ry][3] = pack2(t1.z, t1.w);
            }
            #pragma unroll
            for (int tap = 0; tap < 9; tap++) {
                const int dy = tap / 3, dx = tap % 3;
                const ull* wp = reinterpret_cast<const ull*>(&s_w[(ci*9 + tap)*16 + cog*4]);
                ull w01 = wp[0], w23 = wp[1];
                #pragma unroll
                for (int iy = 0; iy < 2; iy++) {
                    #pragma unroll
                    for (int ix = 0; ix < 2; ix++) {
                        ull vv = pt[iy + dy][ix + dx];
                        ffma2(acc[iy*2 + ix][0], vv, w01);
                        ffma2(acc[iy*2 + ix][1], vv, w23);
                    }
                }
            }
        }
        __syncthreads();
    }

    #pragma unroll
    for (int p = 0; p < 4; p++) {
        const int gy = ty0 + py0 + (p >> 1);
        const int gx = tx0 + px0 + (p & 1);
        float2 a01 = unpack2(acc[p][0]);
        float2 a23 = unpack2(acc[p][1]);
        float4 v4 = make_float4(a01.x, a01.y, a23.x, a23.y);
        if (MODE == 0) {
            size_t pidx = (size_t)img * NHW + gy*64 + gx;  // img = b*T + t
            if (mask[pidx]) v4 = make_float4(0.f, 0.f, 0.f, 0.f);
            *reinterpret_cast<float4*>(&g_value[pidx*NC + zg*16 + cog*4]) = v4;
        } else if (MODE == 1) {
            size_t base = ((size_t)img * NHW + gy*64 + gx) * 288 + zg*16 + cog*4;
            *reinterpret_cast<float4*>(&g_offattn[base]) = v4;
        } else {
            const int co = zg*16 + cog*4;
            size_t base = ((size_t)img * NC + co) * NHW + gy*64 + gx;
            gout[base]            = v4.x;
            gout[base +   NHW]    = v4.y;
            gout[base + 2*NHW]    = v4.z;
            gout[base + 3*NHW]    = v4.w;
        }
    }
}

// ---------------------------------------------------------------------------
// Deformable sampling.  One warp per (b, pixel, head); lane = head channel.
// softmax over T*P=12, flow-guided locations, bilinear zero-pad gather from
// g_value (NHWC -> 128B coalesced per corner), write NCHW g_attnout.
// ---------------------------------------------------------------------------
__global__ __launch_bounds__(256)
void deform_sample(const float* __restrict__ ref,
                   const float* __restrict__ flow_f,
                   const float* __restrict__ flow_b)
{
    const int wg   = blockIdx.x * 8 + (threadIdx.x >> 5);
    const int lane = threadIdx.x & 31;
    const int m   = wg & 7;
    const int pix = (wg >> 3) & 4095;
    const int b   = wg >> 15;

    const float* oa = g_offattn + (size_t)(b * NHW + pix) * 288;

    // softmax over the 12 (t,p) attention logits of this head
    float att[12];
    float mx = -1e30f;
    #pragma unroll
    for (int i = 0; i < 12; i++) { att[i] = oa[192 + m*12 + i]; mx = fmaxf(mx, att[i]); }
    float s = 0.f;
    #pragma unroll
    for (int i = 0; i < 12; i++) { att[i] = __expf(att[i] - mx); s += att[i]; }
    const float inv = 1.0f / s;
    #pragma unroll
    for (int i = 0; i < 12; i++) att[i] *= inv;

    float acc = 0.f;
    const float* vb = g_value + (size_t)(b * NT) * NHW * NC + m*NDH + lane;
    const float* rp = ref + (size_t)(b * NHW + pix) * (NT*2);

    #pragma unroll
    for (int t = 0; t < NT; t++) {
        // flow: t=0 <- flow_backward[b,0,:], t=1 <- 0, t=2 <- flow_forward[b,1,:]
        float fx = 0.f, fy = 0.f;
        if (t == 0) { fx = flow_b[b*16384 + pix];        fy = flow_b[b*16384 + 4096 + pix]; }
        if (t == 2) { fx = flow_f[b*16384 + 8192 + pix]; fy = flow_f[b*16384 + 8192 + 4096 + pix]; }
        // sample coord = ref*W + off + flow - 0.5  (normalizer W=H=64 cancels)
        const float rx = rp[t*2 + 0] * 64.f - 0.5f + fx;
        const float ry = rp[t*2 + 1] * 64.f - 0.5f + fy;
        const float* vt = vb + (size_t)t * NHW * NC;
        #pragma unroll
        for (int p = 0; p < NP; p++) {
            const float sx = rx + oa[(m*NT + t)*8 + p*2 + 0];
            const float sy = ry + oa[(m*NT + t)*8 + p*2 + 1];
            const float x0f = floorf(sx), y0f = floorf(sy);
            const float wx = sx - x0f, wy = sy - y0f;
            const int x0 = (int)x0f, y0 = (int)y0f;
            const float a = att[t*4 + p];
            const float w00 = (1.f - wx) * (1.f - wy) * a;
            const float w10 = wx * (1.f - wy) * a;
            const float w01 = (1.f - wx) * wy * a;
            const float w11 = wx * wy * a;
            const bool xv0 = (unsigned)x0       < 64u;
            const bool xv1 = (unsigned)(x0 + 1) < 64u;
            if ((unsigned)y0 < 64u) {
                const float* r0 = vt + (size_t)(y0*64) * NC;
                if (xv0) acc += w00 * r0[(size_t)x0 * NC];
                if (xv1) acc += w10 * r0[(size_t)(x0 + 1) * NC];
            }
            if ((unsigned)(y0 + 1) < 64u) {
                const float* r1 = vt + (size_t)((y0 + 1)*64) * NC;
                if (xv0) acc += w01 * r1[(size_t)x0 * NC];
                if (xv1) acc += w11 * r1[(size_t)(x0 + 1) * NC];
            }
        }
    }
    g_attnout[(size_t)(b*NC + m*NDH + lane) * NHW + pix] = acc;
}

// ---------------------------------------------------------------------------
// metadata order:
// 0 query 1 reference_points 2 input_flatten 3 spatial_shapes 4 level_start
// 5 padding_mask(bool) 6 flow_forward 7 flow_backward 8 w_value 9 b_value
// 10 w_off 11 b_off 12 w_attn 13 b_attn 14 w_out 15 b_out ; out (B,C,H,W) f32
// ---------------------------------------------------------------------------
extern "C" void kernel_launch(void* const* d_in, const int* in_sizes, int n_in,
                              void* d_out, int out_size)
{
    const float* query         = (const float*)d_in[0];
    const float* refp          = (const float*)d_in[1];
    const float* input_flatten = (const float*)d_in[2];
    const unsigned char* mask  = (const unsigned char*)d_in[5];
    const float* flow_f        = (const float*)d_in[6];
    const float* flow_b        = (const float*)d_in[7];
    const float* w_value       = (const float*)d_in[8];
    const float* b_value       = (const float*)d_in[9];
    const float* w_off         = (const float*)d_in[10];
    const float* b_off         = (const float*)d_in[11];
    const float* w_attn        = (const float*)d_in[12];
    const float* b_attn        = (const float*)d_in[13];
    const float* w_out         = (const float*)d_in[14];
    const float* b_out         = (const float*)d_in[15];
    float* out = (float*)d_out;

    // 1) value conv: 6 images of 256ch -> g_value NHWC (+mask)
    conv3x3<256, 0><<<dim3(4, 4, 6*16), 256>>>(input_flatten, w_value, b_value,
                                               nullptr, nullptr, nullptr, mask);
    // 2) fused offset(192)+attn(96) conv: 2 images of 768ch -> g_offattn
    conv3x3<768, 1><<<dim3(4, 4, 2*18), 256>>>(query, w_off, b_off,
                                               w_attn, b_attn, nullptr, nullptr);
    // 3) deformable sampling: 65536 warps -> g_attnout NCHW
    deform_sample<<<8192, 256>>>(refp, flow_f, flow_b);
    // 4) output conv: 2 images of 256ch -> final d_out NCHW
    conv3x3<256, 2><<<dim3(4, 4, 2*16), 256>>>(nullptr, w_out, b_out,
                                               nullptr, nullptr, out, nullptr);
}

// round 11
// speedup vs baseline: 1.7361x; 1.1372x over previous
#include <cuda_runtime.h>
#include <cuda_bf16.h>
#include <cstdint>

// ---------------------------------------------------------------------------
// MSDeformAttn fusion, R11: convs via mma.sync.m16n8k16 bf16 (hi/lo split for
// fp32 accuracy), staged directly from the original fp32 NCHW tensors.
// Dataflow identical to the passing R3 kernel: g_value NHWC, g_offattn
// [px][288], g_attnout NCHW, deform_sample unchanged, out conv -> NCHW d_out.
// conv as 9 shifted GEMMs: D[128 px][64 co] += X_shift[px][ci] * W_tap[co][ci]
// ---------------------------------------------------------------------------

#define NB   2
#define NT   3
#define NC   256
#define NHW  4096
#define NM   8
#define NP   4
#define NDH  32

typedef uint32_t u32;

// ------------------------------ scratch (.bss) ------------------------------
__device__ __align__(16) float g_value[NB*NT*NHW*NC];     // NHWC per (b,t)
__device__ __align__(16) float g_offattn[NB*NHW*288];     // [px][192 off + 96 attn]
__device__ __align__(16) float g_attnout[NB*NC*NHW];      // NCHW

// ------------------------------- helpers ------------------------------------
__device__ __forceinline__ void split_bf16(float v, __nv_bfloat16& h, __nv_bfloat16& l) {
    h = __float2bfloat16(v);
    l = __float2bfloat16(v - __bfloat162float(h));
}
__device__ __forceinline__ u32 bpack(__nv_bfloat16 a, __nv_bfloat16 b) {
    return (u32)__bfloat16_as_ushort(a) | ((u32)__bfloat16_as_ushort(b) << 16);
}
#define MMA_BF16(c, a, b0_, b1_) \
    asm volatile("mma.sync.aligned.m16n8k16.row.col.f32.bf16.bf16.f32 " \
        "{%0,%1,%2,%3}, {%4,%5,%6,%7}, {%8,%9}, {%0,%1,%2,%3};" \
        : "+f"((c)[0]), "+f"((c)[1]), "+f"((c)[2]), "+f"((c)[3]) \
        : "r"((a)[0]), "r"((a)[1]), "r"((a)[2]), "r"((a)[3]), "r"(b0_), "r"(b1_))

// ---------------------------------------------------------------------------
// conv_hmma: 256 thr; CTA tile 128 px x 64 co; 8 warps 4(m) x 2(n),
// warp tile 32x32 (2 m16 frags x 4 n8 frags).
// K loop: 9 taps x (CIN/32) chunks. Per stage: cooperative staging of
// A[128][32] and B[64][32] as hi/lo bf16 (smem row stride 40 -> conflict-free
// fragment loads), then 2x k16 blocks x 3 split MMAs.
// MODE 0: in=input_flatten NCHW (6 img) -> g_value NHWC (+bias, mask)
// MODE 1: in=query NCHW as 768ch (2 img), couts 288 (192 off | 96 attn),
//         grid.y=5 tiles of 64 (last partial) -> g_offattn [px][288]
// MODE 2: in=g_attnout NCHW (2 img) -> outp NCHW (final d_out, +bias)
// ---------------------------------------------------------------------------
template<int CIN, int MODE>
__global__ __launch_bounds__(256)
void conv_hmma(const float* __restrict__ gin,
               const float* __restrict__ w0, const float* __restrict__ w1,
               const float* __restrict__ bias0, const float* __restrict__ bias1,
               float* __restrict__ outp, const unsigned char* __restrict__ mask)
{
    constexpr int NROWS = (MODE == 1) ? 288 : 256;   // total output channels
    constexpr int NCH = CIN / 32;
    constexpr int NST = 9 * NCH;

    __shared__ __nv_bfloat16 sAh[128*40], sAl[128*40];
    __shared__ __nv_bfloat16 sBh[64*40],  sBl[64*40];

    const int bx  = blockIdx.x;
    const int co0 = blockIdx.y * 64;
    const int img = blockIdx.z;
    const int tid = threadIdx.x, lane = tid & 31, wid = tid >> 5;
    const int wm = wid & 3, wn = wid >> 2;
    const int row0 = wm * 32, ncol0 = wn * 32;
    const int g = lane >> 2, tig = lane & 3;

    const float* src = (MODE == 2) ? (const float*)g_attnout : gin;
    const float* inb = src + (size_t)img * CIN * NHW;

    // staging roles
    const int ar = tid >> 1, ahalf = tid & 1;   // A row (0..127), k-half
    const int pxa = bx * 128 + ar;
    const int aay = pxa >> 6, aax = pxa & 63;
    const int bco = tid >> 2, bq = tid & 3;     // B row (0..63), k-quarter
    const int cob = co0 + bco;
    const bool bact = cob < NROWS;

    float acc[2][4][4];
    #pragma unroll
    for (int mi = 0; mi < 2; ++mi)
        #pragma unroll
        for (int j = 0; j < 4; ++j)
            #pragma unroll
            for (int e = 0; e < 4; ++e) acc[mi][j][e] = 0.f;

    for (int st = 0; st < NST; ++st) {
        const int tap = st / NCH;
        const int ci0 = (st - tap * NCH) * 32;
        const int ky = tap / 3, kx = tap % 3;

        __syncthreads();   // previous stage's MMA reads done
        // ---- stage A: 16 ci values of row ar (half ahalf), hi/lo split ----
        {
            const int sy = aay + ky - 1, sx = aax + kx - 1;
            const bool vld = ((unsigned)sy < 64u) && ((unsigned)sx < 64u);
            const float* p = inb + (size_t)ci0 * NHW + sy * 64 + sx;
            #pragma unroll
            for (int j = 0; j < 8; ++j) {
                const int k = ahalf * 16 + 2 * j;
                float v0 = vld ? p[(size_t)k * NHW]       : 0.f;
                float v1 = vld ? p[(size_t)(k + 1) * NHW] : 0.f;
                __nv_bfloat16 h0, l0, h1, l1;
                split_bf16(v0, h0, l0); split_bf16(v1, h1, l1);
                *(u32*)(sAh + ar * 40 + k) = bpack(h0, h1);
                *(u32*)(sAl + ar * 40 + k) = bpack(l0, l1);
            }
        }
        // ---- stage B: 8 ci values of cout row bco (quarter bq) ----
        {
            #pragma unroll
            for (int j = 0; j < 4; ++j) {
                const int k = bq * 8 + 2 * j;
                float v0 = 0.f, v1 = 0.f;
                if (bact) {
                    const float* wp; size_t base;
                    if (MODE == 1 && cob >= 192) { wp = w1; base = (size_t)(cob - 192) * CIN * 9; }
                    else                         { wp = w0; base = (size_t)cob * CIN * 9; }
                    v0 = wp[base + (size_t)(ci0 + k) * 9 + tap];
                    v1 = wp[base + (size_t)(ci0 + k + 1) * 9 + tap];
                }
                __nv_bfloat16 h0, l0, h1, l1;
                split_bf16(v0, h0, l0); split_bf16(v1, h1, l1);
                *(u32*)(sBh + bco * 40 + k) = bpack(h0, h1);
                *(u32*)(sBl + bco * 40 + k) = bpack(l0, l1);
            }
        }
        __syncthreads();

        // ---- MMA: 2 k16 blocks x (2 m frags x 4 n frags) x 3 split terms ----
        #pragma unroll
        for (int kb = 0; kb < 32; kb += 16) {
            u32 ah[2][4], al[2][4];
            #pragma unroll
            for (int mi = 0; mi < 2; ++mi) {
                const int rr = row0 + mi * 16 + g;
                ah[mi][0] = *(const u32*)(sAh + rr * 40       + kb +     tig * 2);
                ah[mi][1] = *(const u32*)(sAh + (rr + 8) * 40 + kb +     tig * 2);
                ah[mi][2] = *(const u32*)(sAh + rr * 40       + kb + 8 + tig * 2);
                ah[mi][3] = *(const u32*)(sAh + (rr + 8) * 40 + kb + 8 + tig * 2);
                al[mi][0] = *(const u32*)(sAl + rr * 40       + kb +     tig * 2);
                al[mi][1] = *(const u32*)(sAl + (rr + 8) * 40 + kb +     tig * 2);
                al[mi][2] = *(const u32*)(sAl + rr * 40       + kb + 8 + tig * 2);
                al[mi][3] = *(const u32*)(sAl + (rr + 8) * 40 + kb + 8 + tig * 2);
            }
            #pragma unroll
            for (int j = 0; j < 4; ++j) {
                const int nb = ncol0 + j * 8 + g;
                u32 bh0 = *(const u32*)(sBh + nb * 40 + kb +     tig * 2);
                u32 bh1 = *(const u32*)(sBh + nb * 40 + kb + 8 + tig * 2);
                u32 bl0 = *(const u32*)(sBl + nb * 40 + kb +     tig * 2);
                u32 bl1 = *(const u32*)(sBl + nb * 40 + kb + 8 + tig * 2);
                #pragma unroll
                for (int mi = 0; mi < 2; ++mi) {
                    MMA_BF16(acc[mi][j], ah[mi], bh0, bh1);
                    MMA_BF16(acc[mi][j], al[mi], bh0, bh1);
                    MMA_BF16(acc[mi][j], ah[mi], bl0, bl1);
                }
            }
        }
    }

    // ------------------------------ epilogue -------------------------------
    #pragma unroll
    for (int mi = 0; mi < 2; ++mi) {
        const int px1 = bx * 128 + row0 + mi * 16 + g;
        const int px2 = px1 + 8;
        bool mz1 = false, mz2 = false;
        if (MODE == 0) {
            mz1 = mask[img * NHW + px1] != 0;
            mz2 = mask[img * NHW + px2] != 0;
        }
        #pragma unroll
        for (int j = 0; j < 4; ++j) {
            const int co = co0 + ncol0 + j * 8 + tig * 2;
            if (MODE == 1 && co >= 288) continue;
            float b0v, b1v;
            if (MODE == 1) {
                if (co < 192) { b0v = bias0[co];      b1v = bias0[co + 1]; }
                else          { b0v = bias1[co - 192]; b1v = bias1[co - 191]; }
            } else { b0v = bias0[co]; b1v = bias0[co + 1]; }
            float o00 = acc[mi][j][0] + b0v, o01 = acc[mi][j][1] + b1v;
            float o10 = acc[mi][j][2] + b0v, o11 = acc[mi][j][3] + b1v;
            if (MODE == 0) {
                if (mz1) { o00 = 0.f; o01 = 0.f; }
                if (mz2) { o10 = 0.f; o11 = 0.f; }
                *(float2*)&g_value[((size_t)img * NHW + px1) * NC + co] = make_float2(o00, o01);
                *(float2*)&g_value[((size_t)img * NHW + px2) * NC + co] = make_float2(o10, o11);
            } else if (MODE == 1) {
                *(float2*)&g_offattn[((size_t)img * NHW + px1) * 288 + co] = make_float2(o00, o01);
                *(float2*)&g_offattn[((size_t)img * NHW + px2) * 288 + co] = make_float2(o10, o11);
            } else {
                outp[((size_t)img * NC + co)     * NHW + px1] = o00;
                outp[((size_t)img * NC + co + 1) * NHW + px1] = o01;
                outp[((size_t)img * NC + co)     * NHW + px2] = o10;
                outp[((size_t)img * NC + co + 1) * NHW + px2] = o11;
            }
        }
    }
}

// ---------------------------------------------------------------------------
// Deformable sampling — byte-for-byte the R3-passing version.
// One warp per (b, pixel, head); lane = head channel. NCHW g_attnout write.
// ---------------------------------------------------------------------------
__global__ __launch_bounds__(256)
void deform_sample(const float* __restrict__ ref,
                   const float* __restrict__ flow_f,
                   const float* __restrict__ flow_b)
{
    const int wg   = blockIdx.x * 8 + (threadIdx.x >> 5);
    const int lane = threadIdx.x & 31;
    const int m   = wg & 7;
    const int pix = (wg >> 3) & 4095;
    const int b   = wg >> 15;

    const float* oa = g_offattn + (size_t)(b * NHW + pix) * 288;

    float att[12];
    float mx = -1e30f;
    #pragma unroll
    for (int i = 0; i < 12; i++) { att[i] = oa[192 + m*12 + i]; mx = fmaxf(mx, att[i]); }
    float s = 0.f;
    #pragma unroll
    for (int i = 0; i < 12; i++) { att[i] = __expf(att[i] - mx); s += att[i]; }
    const float inv = 1.0f / s;
    #pragma unroll
    for (int i = 0; i < 12; i++) att[i] *= inv;

    float acc = 0.f;
    const float* vb = g_value + (size_t)(b * NT) * NHW * NC + m*NDH + lane;
    const float* rp = ref + (size_t)(b * NHW + pix) * (NT*2);

    #pragma unroll
    for (int t = 0; t < NT; t++) {
        float fx = 0.f, fy = 0.f;
        if (t == 0) { fx = flow_b[b*16384 + pix];        fy = flow_b[b*16384 + 4096 + pix]; }
        if (t == 2) { fx = flow_f[b*16384 + 8192 + pix]; fy = flow_f[b*16384 + 8192 + 4096 + pix]; }
        const float rx = rp[t*2 + 0] * 64.f - 0.5f + fx;
        const float ry = rp[t*2 + 1] * 64.f - 0.5f + fy;
        const float* vt = vb + (size_t)t * NHW * NC;
        #pragma unroll
        for (int p = 0; p < NP; p++) {
            const float sx = rx + oa[(m*NT + t)*8 + p*2 + 0];
            const float sy = ry + oa[(m*NT + t)*8 + p*2 + 1];
            const float x0f = floorf(sx), y0f = floorf(sy);
            const float wx = sx - x0f, wy = sy - y0f;
            const int x0 = (int)x0f, y0 = (int)y0f;
            const float a = att[t*4 + p];
            const float w00 = (1.f - wx) * (1.f - wy) * a;
            const float w10 = wx * (1.f - wy) * a;
            const float w01 = (1.f - wx) * wy * a;
            const float w11 = wx * wy * a;
            const bool xv0 = (unsigned)x0       < 64u;
            const bool xv1 = (unsigned)(x0 + 1) < 64u;
            if ((unsigned)y0 < 64u) {
                const float* r0 = vt + (size_t)(y0*64) * NC;
                if (xv0) acc += w00 * r0[(size_t)x0 * NC];
                if (xv1) acc += w10 * r0[(size_t)(x0 + 1) * NC];
            }
            if ((unsigned)(y0 + 1) < 64u) {
                const float* r1 = vt + (size_t)((y0 + 1)*64) * NC;
                if (xv0) acc += w01 * r1[(size_t)x0 * NC];
                if (xv1) acc += w11 * r1[(size_t)(x0 + 1) * NC];
            }
        }
    }
    g_attnout[(size_t)(b*NC + m*NDH + lane) * NHW + pix] = acc;
}

// ---------------------------------------------------------------------------
// metadata order:
// 0 query 1 reference_points 2 input_flatten 3 spatial_shapes 4 level_start
// 5 padding_mask(bool) 6 flow_forward 7 flow_backward 8 w_value 9 b_value
// 10 w_off 11 b_off 12 w_attn 13 b_attn 14 w_out 15 b_out ; out (B,C,H,W) f32
// ---------------------------------------------------------------------------
extern "C" void kernel_launch(void* const* d_in, const int* in_sizes, int n_in,
                              void* d_out, int out_size)
{
    const float* query         = (const float*)d_in[0];
    const float* refp          = (const float*)d_in[1];
    const float* input_flatten = (const float*)d_in[2];
    const unsigned char* mask  = (const unsigned char*)d_in[5];
    const float* flow_f        = (const float*)d_in[6];
    const float* flow_b        = (const float*)d_in[7];
    const float* w_value       = (const float*)d_in[8];
    const float* b_value       = (const float*)d_in[9];
    const float* w_off         = (const float*)d_in[10];
    const float* b_off         = (const float*)d_in[11];
    const float* w_attn        = (const float*)d_in[12];
    const float* b_attn        = (const float*)d_in[13];
    const float* w_out         = (const float*)d_in[14];
    const float* b_out         = (const float*)d_in[15];
    float* out = (float*)d_out;

    // 1) value conv: NCHW fp32 -> g_value NHWC (+bias, mask)
    conv_hmma<256, 0><<<dim3(32, 4, 6), 256>>>(input_flatten, w_value, nullptr,
                                               b_value, nullptr, nullptr, mask);
    // 2) off(192)+attn(96) conv -> g_offattn [px][288] (5th tile partial)
    conv_hmma<768, 1><<<dim3(32, 5, 2), 256>>>(query, w_off, w_attn,
                                               b_off, b_attn, nullptr, nullptr);
    // 3) deformable sampling -> g_attnout NCHW
    deform_sample<<<8192, 256>>>(refp, flow_f, flow_b);
    // 4) out conv -> d_out NCHW (+bias)
    conv_hmma<256, 2><<<dim3(32, 4, 2), 256>>>(nullptr, w_out, nullptr,
                                               b_out, nullptr, out, nullptr);
}

// round 13
// speedup vs baseline: 1.8827x; 1.0844x over previous
#include <cuda_runtime.h>
#include <cuda_bf16.h>
#include <cstdint>

// ---------------------------------------------------------------------------
// MSDeformAttn fusion, R12: R11's proven HMMA conv core (mma.sync m16n8k16
// bf16 hi/lo split) + double-buffered smem with register prefetch so global
// staging overlaps MMA.  Dataflow unchanged: g_value NHWC, g_offattn
// [px][288], g_attnout NCHW, deform_sample identical.
// ---------------------------------------------------------------------------

#define NB   2
#define NT   3
#define NC   256
#define NHW  4096
#define NM   8
#define NP   4
#define NDH  32

typedef uint32_t u32;

// ------------------------------ scratch (.bss) ------------------------------
__device__ __align__(16) float g_value[NB*NT*NHW*NC];     // NHWC per (b,t)
__device__ __align__(16) float g_offattn[NB*NHW*288];     // [px][192 off + 96 attn]
__device__ __align__(16) float g_attnout[NB*NC*NHW];      // NCHW

// ------------------------------- helpers ------------------------------------
__device__ __forceinline__ void split_bf16(float v, __nv_bfloat16& h, __nv_bfloat16& l) {
    h = __float2bfloat16(v);
    l = __float2bfloat16(v - __bfloat162float(h));
}
__device__ __forceinline__ u32 bpack(__nv_bfloat16 a, __nv_bfloat16 b) {
    return (u32)__bfloat16_as_ushort(a) | ((u32)__bfloat16_as_ushort(b) << 16);
}
#define MMA_BF16(c, a, b0_, b1_) \
    asm volatile("mma.sync.aligned.m16n8k16.row.col.f32.bf16.bf16.f32 " \
        "{%0,%1,%2,%3}, {%4,%5,%6,%7}, {%8,%9}, {%0,%1,%2,%3};" \
        : "+f"((c)[0]), "+f"((c)[1]), "+f"((c)[2]), "+f"((c)[3]) \
        : "r"((a)[0]), "r"((a)[1]), "r"((a)[2]), "r"((a)[3]), "r"(b0_), "r"(b1_))

// smem layout constants (bf16 elements)
#define SA   (128*40)
#define SB   (64*40)
#define SBUF (2*SA + 2*SB)              // one pipeline buffer
#define SMEM_BYTES (2 * SBUF * 2)       // 61440 bytes

// ---------------------------------------------------------------------------
// conv_hmma: 256 thr; CTA tile 128 px x 64 co; 8 warps 4(m) x 2(n),
// warp tile 32x32.  K loop: 9 taps x (CIN/32) chunks, software-pipelined:
// regs(st) -> smem[st&1]; prefetch regs(st+1); sync; MMA on smem[st&1].
// 3 MMAs per k16: Ah*Bh + Al*Bh + Ah*Bl  (fp32-accurate hi/lo split).
// MODE 0: in=input_flatten NCHW (6 img) -> g_value NHWC (+bias, mask)
// MODE 1: in=query NCHW 768ch (2 img), couts 288 (192 off | 96 attn)
// MODE 2: in=g_attnout NCHW (2 img) -> outp NCHW (final d_out, +bias)
// ---------------------------------------------------------------------------
template<int CIN, int MODE>
__global__ __launch_bounds__(256, 2)
void conv_hmma(const float* __restrict__ gin,
               const float* __restrict__ w0, const float* __restrict__ w1,
               const float* __restrict__ bias0, const float* __restrict__ bias1,
               float* __restrict__ outp, const unsigned char* __restrict__ mask)
{
    constexpr int NROWS = (MODE == 1) ? 288 : 256;
    constexpr int NCH = CIN / 32;
    constexpr int NST = 9 * NCH;

    extern __shared__ char dsm[];
    __nv_bfloat16* sbase = (__nv_bfloat16*)dsm;

    const int bx  = blockIdx.x;
    const int co0 = blockIdx.y * 64;
    const int img = blockIdx.z;
    const int tid = threadIdx.x, lane = tid & 31, wid = tid >> 5;
    const int wm = wid & 3, wn = wid >> 2;
    const int row0 = wm * 32, ncol0 = wn * 32;
    const int g = lane >> 2, tig = lane & 3;

    const float* src = (MODE == 2) ? (const float*)g_attnout : gin;
    const float* inb = src + (size_t)img * CIN * NHW;

    // staging roles
    const int ar = tid >> 1, ahalf = tid & 1;   // A row (0..127), k-half
    const int pxa = bx * 128 + ar;
    const int aay = pxa >> 6, aax = pxa & 63;
    const int bco = tid >> 2, bq = tid & 3;     // B row (0..63), k-quarter
    const int cob = co0 + bco;
    const bool bact = cob < NROWS;

    // B weight source pointer (constant across stages)
    const float* wsrc; size_t wbase = 0;
    if (MODE == 1 && cob >= 192) { wsrc = w1; wbase = (size_t)(cob - 192) * CIN * 9; }
    else                         { wsrc = w0; wbase = (size_t)cob * CIN * 9; }

    float acc[2][4][4];
    #pragma unroll
    for (int mi = 0; mi < 2; ++mi)
        #pragma unroll
        for (int j = 0; j < 4; ++j)
            #pragma unroll
            for (int e = 0; e < 4; ++e) acc[mi][j][e] = 0.f;

    float va[16], vb[8];

    // ---- prefetch stage st into registers ----
    auto load_stage = [&](int st) {
        const int tap = st / NCH;
        const int ci0 = (st - tap * NCH) * 32;
        const int ky = tap / 3, kx = tap % 3;
        const int sy = aay + ky - 1, sx = aax + kx - 1;
        const bool vld = ((unsigned)sy < 64u) && ((unsigned)sx < 64u);
        const float* p = inb + (size_t)ci0 * NHW + sy * 64 + sx;
        #pragma unroll
        for (int j = 0; j < 16; ++j)
            va[j] = vld ? p[(size_t)(ahalf * 16 + j) * NHW] : 0.f;
        if (bact) {
            #pragma unroll
            for (int j = 0; j < 8; ++j)
                vb[j] = wsrc[wbase + (size_t)(ci0 + bq * 8 + j) * 9 + tap];
        } else {
            #pragma unroll
            for (int j = 0; j < 8; ++j) vb[j] = 0.f;
        }
    };

    load_stage(0);

    for (int st = 0; st < NST; ++st) {
        __nv_bfloat16* Ah = sbase + (st & 1) * SBUF;
        __nv_bfloat16* Al = Ah + SA;
        __nv_bfloat16* Bh = Al + SA;
        __nv_bfloat16* Bl = Bh + SB;

        // ---- store prefetched regs -> smem buf ----
        #pragma unroll
        for (int j = 0; j < 8; ++j) {
            const int k = ahalf * 16 + 2 * j;
            __nv_bfloat16 h0, l0, h1, l1;
            split_bf16(va[2*j], h0, l0); split_bf16(va[2*j+1], h1, l1);
            *(u32*)(Ah + ar * 40 + k) = bpack(h0, h1);
            *(u32*)(Al + ar * 40 + k) = bpack(l0, l1);
        }
        #pragma unroll
        for (int j = 0; j < 4; ++j) {
            const int k = bq * 8 + 2 * j;
            __nv_bfloat16 h0, l0, h1, l1;
            split_bf16(vb[2*j], h0, l0); split_bf16(vb[2*j+1], h1, l1);
            *(u32*)(Bh + bco * 40 + k) = bpack(h0, h1);
            *(u32*)(Bl + bco * 40 + k) = bpack(l0, l1);
        }

        if (st + 1 < NST) load_stage(st + 1);   // overlaps with MMA below
        __syncthreads();

        // ---- MMA: 2 k16 blocks x (2 m frags x 4 n frags) x 3 split terms ----
        #pragma unroll
        for (int kb = 0; kb < 32; kb += 16) {
            u32 ah[2][4], al[2][4];
            #pragma unroll
            for (int mi = 0; mi < 2; ++mi) {
                const int rr = row0 + mi * 16 + g;
                ah[mi][0] = *(const u32*)(Ah + rr * 40       + kb +     tig * 2);
                ah[mi][1] = *(const u32*)(Ah + (rr + 8) * 40 + kb +     tig * 2);
                ah[mi][2] = *(const u32*)(Ah + rr * 40       + kb + 8 + tig * 2);
                ah[mi][3] = *(const u32*)(Ah + (rr + 8) * 40 + kb + 8 + tig * 2);
                al[mi][0] = *(const u32*)(Al + rr * 40       + kb +     tig * 2);
                al[mi][1] = *(const u32*)(Al + (rr + 8) * 40 + kb +     tig * 2);
                al[mi][2] = *(const u32*)(Al + rr * 40       + kb + 8 + tig * 2);
                al[mi][3] = *(const u32*)(Al + (rr + 8) * 40 + kb + 8 + tig * 2);
            }
            #pragma unroll
            for (int j = 0; j < 4; ++j) {
                const int nb = ncol0 + j * 8 + g;
                u32 bh0 = *(const u32*)(Bh + nb * 40 + kb +     tig * 2);
                u32 bh1 = *(const u32*)(Bh + nb * 40 + kb + 8 + tig * 2);
                u32 bl0 = *(const u32*)(Bl + nb * 40 + kb +     tig * 2);
                u32 bl1 = *(const u32*)(Bl + nb * 40 + kb + 8 + tig * 2);
                #pragma unroll
                for (int mi = 0; mi < 2; ++mi) {
                    MMA_BF16(acc[mi][j], ah[mi], bh0, bh1);
                    MMA_BF16(acc[mi][j], al[mi], bh0, bh1);
                    MMA_BF16(acc[mi][j], ah[mi], bl0, bl1);
                }
            }
        }
    }

    // ------------------------------ epilogue -------------------------------
    #pragma unroll
    for (int mi = 0; mi < 2; ++mi) {
        const int px1 = bx * 128 + row0 + mi * 16 + g;
        const int px2 = px1 + 8;
        bool mz1 = false, mz2 = false;
        if (MODE == 0) {
            mz1 = mask[img * NHW + px1] != 0;
            mz2 = mask[img * NHW + px2] != 0;
        }
        #pragma unroll
        for (int j = 0; j < 4; ++j) {
            const int co = co0 + ncol0 + j * 8 + tig * 2;
            if (MODE == 1 && co >= 288) continue;
            float b0v, b1v;
            if (MODE == 1) {
                if (co < 192) { b0v = bias0[co];       b1v = bias0[co + 1]; }
                else          { b0v = bias1[co - 192]; b1v = bias1[co - 191]; }
            } else { b0v = bias0[co]; b1v = bias0[co + 1]; }
            float o00 = acc[mi][j][0] + b0v, o01 = acc[mi][j][1] + b1v;
            float o10 = acc[mi][j][2] + b0v, o11 = acc[mi][j][3] + b1v;
            if (MODE == 0) {
                if (mz1) { o00 = 0.f; o01 = 0.f; }
                if (mz2) { o10 = 0.f; o11 = 0.f; }
                *(float2*)&g_value[((size_t)img * NHW + px1) * NC + co] = make_float2(o00, o01);
                *(float2*)&g_value[((size_t)img * NHW + px2) * NC + co] = make_float2(o10, o11);
            } else if (MODE == 1) {
                *(float2*)&g_offattn[((size_t)img * NHW + px1) * 288 + co] = make_float2(o00, o01);
                *(float2*)&g_offattn[((size_t)img * NHW + px2) * 288 + co] = make_float2(o10, o11);
            } else {
                outp[((size_t)img * NC + co)     * NHW + px1] = o00;
                outp[((size_t)img * NC + co + 1) * NHW + px1] = o01;
                outp[((size_t)img * NC + co)     * NHW + px2] = o10;
                outp[((size_t)img * NC + co + 1) * NHW + px2] = o11;
            }
        }
    }
}

// ---------------------------------------------------------------------------
// Deformable sampling — unchanged (proven).  Warp = (b, pixel, head).
// ---------------------------------------------------------------------------
__global__ __launch_bounds__(256)
void deform_sample(const float* __restrict__ ref,
                   const float* __restrict__ flow_f,
                   const float* __restrict__ flow_b)
{
    const int wg   = blockIdx.x * 8 + (threadIdx.x >> 5);
    const int lane = threadIdx.x & 31;
    const int m   = wg & 7;
    const int pix = (wg >> 3) & 4095;
    const int b   = wg >> 15;

    const float* oa = g_offattn + (size_t)(b * NHW + pix) * 288;

    float att[12];
    float mx = -1e30f;
    #pragma unroll
    for (int i = 0; i < 12; i++) { att[i] = oa[192 + m*12 + i]; mx = fmaxf(mx, att[i]); }
    float s = 0.f;
    #pragma unroll
    for (int i = 0; i < 12; i++) { att[i] = __expf(att[i] - mx); s += att[i]; }
    const float inv = 1.0f / s;
    #pragma unroll
    for (int i = 0; i < 12; i++) att[i] *= inv;

    float acc = 0.f;
    const float* vb = g_value + (size_t)(b * NT) * NHW * NC + m*NDH + lane;
    const float* rp = ref + (size_t)(b * NHW + pix) * (NT*2);

    #pragma unroll
    for (int t = 0; t < NT; t++) {
        float fx = 0.f, fy = 0.f;
        if (t == 0) { fx = flow_b[b*16384 + pix];        fy = flow_b[b*16384 + 4096 + pix]; }
        if (t == 2) { fx = flow_f[b*16384 + 8192 + pix]; fy = flow_f[b*16384 + 8192 + 4096 + pix]; }
        const float rx = rp[t*2 + 0] * 64.f - 0.5f + fx;
        const float ry = rp[t*2 + 1] * 64.f - 0.5f + fy;
        const float* vt = vb + (size_t)t * NHW * NC;
        #pragma unroll
        for (int p = 0; p < NP; p++) {
            const float sx = rx + oa[(m*NT + t)*8 + p*2 + 0];
            const float sy = ry + oa[(m*NT + t)*8 + p*2 + 1];
            const float x0f = floorf(sx), y0f = floorf(sy);
            const float wx = sx - x0f, wy = sy - y0f;
            const int x0 = (int)x0f, y0 = (int)y0f;
            const float a = att[t*4 + p];
            const float w00 = (1.f - wx) * (1.f - wy) * a;
            const float w10 = wx * (1.f - wy) * a;
            const float w01 = (1.f - wx) * wy * a;
            const float w11 = wx * wy * a;
            const bool xv0 = (unsigned)x0       < 64u;
            const bool xv1 = (unsigned)(x0 + 1) < 64u;
            if ((unsigned)y0 < 64u) {
                const float* r0 = vt + (size_t)(y0*64) * NC;
                if (xv0) acc += w00 * r0[(size_t)x0 * NC];
                if (xv1) acc += w10 * r0[(size_t)(x0 + 1) * NC];
            }
            if ((unsigned)(y0 + 1) < 64u) {
                const float* r1 = vt + (size_t)((y0 + 1)*64) * NC;
                if (xv0) acc += w01 * r1[(size_t)x0 * NC];
                if (xv1) acc += w11 * r1[(size_t)(x0 + 1) * NC];
            }
        }
    }
    g_attnout[(size_t)(b*NC + m*NDH + lane) * NHW + pix] = acc;
}

// ---------------------------------------------------------------------------
extern "C" void kernel_launch(void* const* d_in, const int* in_sizes, int n_in,
                              void* d_out, int out_size)
{
    const float* query         = (const float*)d_in[0];
    const float* refp          = (const float*)d_in[1];
    const float* input_flatten = (const float*)d_in[2];
    const unsigned char* mask  = (const unsigned char*)d_in[5];
    const float* flow_f        = (const float*)d_in[6];
    const float* flow_b        = (const float*)d_in[7];
    const float* w_value       = (const float*)d_in[8];
    const float* b_value       = (const float*)d_in[9];
    const float* w_off         = (const float*)d_in[10];
    const float* b_off         = (const float*)d_in[11];
    const float* w_attn        = (const float*)d_in[12];
    const float* b_attn        = (const float*)d_in[13];
    const float* w_out         = (const float*)d_in[14];
    const float* b_out         = (const float*)d_in[15];
    float* out = (float*)d_out;

    static bool attr_done = false;
    if (!attr_done) {
        cudaFuncSetAttribute(conv_hmma<256,0>, cudaFuncAttributeMaxDynamicSharedMemorySize, SMEM_BYTES);
        cudaFuncSetAttribute(conv_hmma<768,1>, cudaFuncAttributeMaxDynamicSharedMemorySize, SMEM_BYTES);
        cudaFuncSetAttribute(conv_hmma<256,2>, cudaFuncAttributeMaxDynamicSharedMemorySize, SMEM_BYTES);
        attr_done = true;
    }

    // 1) value conv: NCHW fp32 -> g_value NHWC (+bias, mask)
    conv_hmma<256, 0><<<dim3(32, 4, 6), 256, SMEM_BYTES>>>(
        input_flatten, w_value, nullptr, b_value, nullptr, nullptr, mask);
    // 2) off(192)+attn(96) conv -> g_offattn [px][288]
    conv_hmma<768, 1><<<dim3(32, 5, 2), 256, SMEM_BYTES>>>(
        query, w_off, w_attn, b_off, b_attn, nullptr, nullptr);
    // 3) deformable sampling -> g_attnout NCHW
    deform_sample<<<8192, 256>>>(refp, flow_f, flow_b);
    // 4) out conv -> d_out NCHW (+bias)
    conv_hmma<256, 2><<<dim3(32, 4, 2), 256, SMEM_BYTES>>>(
        nullptr, w_out, nullptr, b_out, nullptr, out, nullptr);
}